// round 8
// baseline (speedup 1.0000x reference)
#include <cuda_runtime.h>
#include <math.h>

#define NPTS     4096
#define NB       16
#define NCLOUD   32
#define NBINS    128
#define SORT_TPB 256
#define MAIN_TPB 128
#define MAIN_GRID 1024   // 32 cloud-pairs * 32 blocks; 4 warps/block, 32 queries/warp

__device__ __align__(16) float g_sx[NCLOUD][NPTS];
__device__ __align__(16) float g_sy[NCLOUD][NPTS];
__device__ __align__(16) float g_sz[NCLOUD][NPTS];
__device__ __align__(16) float g_su[NCLOUD][NPTS];
__device__ int   g_binstart[NCLOUD][NBINS + 1];
__device__ float g_zmin[NCLOUD];
__device__ float g_binw[NCLOUD];
__device__ float g_accum;       // zero at entry/exit of every launch
__device__ unsigned g_count;    // zero at entry/exit of every launch

typedef unsigned long long u64;

static __device__ __forceinline__ u64 bcast2(float v) {
    u64 r;
    asm("mov.b64 %0, {%1, %1};" : "=l"(r) : "f"(v));
    return r;
}
static __device__ __forceinline__ void unpack2(u64 v, float &lo, float &hi) {
    asm("mov.b64 {%0, %1}, %2;" : "=f"(lo), "=f"(hi) : "l"(v));
}
static __device__ __forceinline__ u64 fma2(u64 a, u64 b, u64 c) {
    u64 d;
    asm("fma.rn.f32x2 %0, %1, %2, %3;" : "=l"(d) : "l"(a), "l"(b), "l"(c));
    return d;
}

// ---------------- sort kernel: bucket each cloud by z into NBINS bins -------
__global__ void __launch_bounds__(SORT_TPB) sort_kernel(const float* __restrict__ tpl,
                                                        const float* __restrict__ src) {
    const int c = blockIdx.x;   // 0..15 = template batches, 16..31 = source
    const float* P = (c < NB) ? (tpl + (size_t)c * NPTS * 3)
                              : (src + (size_t)(c - NB) * NPTS * 3);
    __shared__ float rmin[SORT_TPB / 32], rmax[SORT_TPB / 32];
    __shared__ int hist[NBINS];
    __shared__ int scan_a[NBINS], scan_b[NBINS];
    __shared__ int boff[NBINS + 1];
    __shared__ float s_zmin, s_inv;

    const int tid = threadIdx.x;
    float mn = 3.4e38f, mx = -3.4e38f;
    for (int p = tid; p < NPTS; p += SORT_TPB) {
        float z = P[3 * p + 2];
        mn = fminf(mn, z);
        mx = fmaxf(mx, z);
    }
#pragma unroll
    for (int o = 16; o; o >>= 1) {
        mn = fminf(mn, __shfl_xor_sync(0xffffffffu, mn, o));
        mx = fmaxf(mx, __shfl_xor_sync(0xffffffffu, mx, o));
    }
    if ((tid & 31) == 0) { rmin[tid >> 5] = mn; rmax[tid >> 5] = mx; }
    if (tid < NBINS) hist[tid] = 0;
    __syncthreads();
    if (tid == 0) {
        float zmin = rmin[0], zmax = rmax[0];
        for (int w = 1; w < SORT_TPB / 32; w++) {
            zmin = fminf(zmin, rmin[w]);
            zmax = fmaxf(zmax, rmax[w]);
        }
        float binw = fmaxf((zmax - zmin) / NBINS, 1e-30f);
        s_zmin = zmin;
        s_inv = 1.0f / binw;
        g_zmin[c] = zmin;
        g_binw[c] = binw;
    }
    __syncthreads();
    const float zmin = s_zmin, inv = s_inv;

    for (int p = tid; p < NPTS; p += SORT_TPB) {
        float z = P[3 * p + 2];
        int bn = min(max((int)((z - zmin) * inv), 0), NBINS - 1);
        atomicAdd(&hist[bn], 1);
    }
    __syncthreads();

    // parallel inclusive scan (Hillis-Steele) over NBINS
    if (tid < NBINS) scan_a[tid] = hist[tid];
    __syncthreads();
    int* cur = scan_a;
    int* nxt = scan_b;
#pragma unroll
    for (int off = 1; off < NBINS; off <<= 1) {
        if (tid < NBINS)
            nxt[tid] = (tid >= off) ? cur[tid] + cur[tid - off] : cur[tid];
        __syncthreads();
        int* t = cur; cur = nxt; nxt = t;
    }
    if (tid < NBINS) boff[tid] = cur[tid] - hist[tid];   // exclusive
    if (tid == 0) boff[NBINS] = NPTS;
    __syncthreads();
    if (tid < NBINS) hist[tid] = 0;
    __syncthreads();

    for (int p = tid; p < NPTS; p += SORT_TPB) {
        float x = P[3 * p + 0], y = P[3 * p + 1], z = P[3 * p + 2];
        int bn = min(max((int)((z - zmin) * inv), 0), NBINS - 1);
        int idx = boff[bn] + atomicAdd(&hist[bn], 1);
        g_sx[c][idx] = x;
        g_sy[c][idx] = y;
        g_sz[c][idx] = z;
        g_su[c][idx] = x * x + y * y + z * z;
    }
    for (int k = tid; k <= NBINS; k += SORT_TPB) g_binstart[c][k] = boff[k];
}

// ---------------- main kernel: windowed NN scan with batched expansion ------
__global__ void __launch_bounds__(MAIN_TPB) chamfer_main(float* __restrict__ out) {
    const int tid = threadIdx.x;
    const int b = blockIdx.x;
    const int pair = b >> 5;                 // 0..31
    const int blk  = b & 31;                 // block within pair
    const int dir = pair >> 4;
    const int batch = pair & 15;
    const int qcl = (dir == 0) ? batch : NB + batch;
    const int dcl = (dir == 0) ? NB + batch : batch;

    const int warp = tid >> 5, lane = tid & 31;
    const int q = blk * MAIN_TPB + warp * 32 + lane;   // sorted query index

    const float qz = __ldg(&g_sz[qcl][q]);
    const float qu = __ldg(&g_su[qcl][q]);
    const u64 pqx = bcast2(-2.0f * __ldg(&g_sx[qcl][q]));
    const u64 pqy = bcast2(-2.0f * __ldg(&g_sy[qcl][q]));
    const u64 pqz = bcast2(-2.0f * qz);

    const float zmin = g_zmin[dcl];
    const float binw = g_binw[dcl];
    const float invw = 1.0f / binw;
    const int* bins = g_binstart[dcl];

    float wlo = qz, whi = qz;
#pragma unroll
    for (int o = 16; o; o >>= 1) {
        wlo = fminf(wlo, __shfl_xor_sync(0xffffffffu, wlo, o));
        whi = fmaxf(whi, __shfl_xor_sync(0xffffffffu, whi, o));
    }
    int lo = min(max((int)((wlo - zmin) * invw), 0), NBINS - 1);
    int hi = min(max((int)((whi - zmin) * invw), 0), NBINS - 1);

    float bA = 3.4e38f, bB = 3.4e38f;
    const ulonglong2* vx = (const ulonglong2*)g_sx[dcl];
    const ulonglong2* vy = (const ulonglong2*)g_sy[dcl];
    const ulonglong2* vz = (const ulonglong2*)g_sz[dcl];
    const ulonglong2* vu = (const ulonglong2*)g_su[dcl];

    auto scan = [&](int a, int e) {
        int j1 = (e + 3) >> 2;
#pragma unroll 2
        for (int j = a >> 2; j < j1; j++) {
            ulonglong2 bx = __ldg(&vx[j]);
            ulonglong2 by = __ldg(&vy[j]);
            ulonglong2 bz = __ldg(&vz[j]);
            ulonglong2 bu = __ldg(&vu[j]);
            u64 a01 = fma2(pqz, bz.x, bu.x);
            a01 = fma2(pqy, by.x, a01);
            a01 = fma2(pqx, bx.x, a01);
            u64 a23 = fma2(pqz, bz.y, bu.y);
            a23 = fma2(pqy, by.y, a23);
            a23 = fma2(pqx, bx.y, a23);
            float l0, h0, l1, h1;
            unpack2(a01, l0, h0);
            unpack2(a23, l1, h1);
            bA = fminf(bA, fminf(l0, l1));
            bB = fminf(bB, fminf(h0, h1));
        }
    };

    // initial window: bins spanned by the warp's queries
    scan(__ldg(&bins[lo]), __ldg(&bins[hi + 1]));

    // batched expansion: admit ALL bins within radius r = sqrt(warp_max(dist2))
    // each round; m only shrinks, so a stable window is final.
    while (true) {
        float m = qu + fminf(bA, bB);
#pragma unroll
        for (int o = 16; o; o >>= 1) m = fmaxf(m, __shfl_xor_sync(0xffffffffu, m, o));
        m = fmaxf(m, 0.0f);
        float r = sqrtf(m) * 1.0001f + 1e-12f;
        int nlo = max(min((int)((wlo - r - zmin) * invw), NBINS - 1), 0);
        int nhi = min(max((int)((whi + r - zmin) * invw), 0), NBINS - 1);
        bool grewL = nlo < lo, grewR = nhi > hi;
        if (!grewL && !grewR) break;
        if (grewL) {
            scan(__ldg(&bins[nlo]), __ldg(&bins[lo]));
            lo = nlo;
        }
        if (grewR) {
            scan(__ldg(&bins[hi + 1]), __ldg(&bins[nhi + 1]));
            hi = nhi;
        }
    }

    float s = sqrtf(fmaxf(qu + fminf(bA, bB), 0.0f));

    // block reduction (4 warps)
#pragma unroll
    for (int o = 16; o; o >>= 1) s += __shfl_xor_sync(0xffffffffu, s, o);
    __shared__ float red[MAIN_TPB / 32];
    if (lane == 0) red[warp] = s;
    __syncthreads();
    if (tid == 0) {
        float t = 0.0f;
#pragma unroll
        for (int w = 0; w < MAIN_TPB / 32; w++) t += red[w];
        atomicAdd(&g_accum, t);
        __threadfence();
        unsigned old = atomicAdd(&g_count, 1u);
        if (old == MAIN_GRID - 1) {
            __threadfence();
            float total = atomicAdd(&g_accum, 0.0f);
            out[0] = total * (1.0f / 131072.0f);   // / (2*16*4096)
            g_accum = 0.0f;
            __threadfence();
            atomicExch(&g_count, 0u);
        }
    }
}

extern "C" void kernel_launch(void* const* d_in, const int* in_sizes, int n_in,
                              void* d_out, int out_size) {
    const float* tpl = (const float*)d_in[0];
    const float* src = (const float*)d_in[1];
    (void)in_sizes; (void)n_in; (void)out_size;

    sort_kernel<<<NCLOUD, SORT_TPB>>>(tpl, src);
    chamfer_main<<<MAIN_GRID, MAIN_TPB>>>((float*)d_out);
}

// round 9
// speedup vs baseline: 1.7851x; 1.7851x over previous
#include <cuda_runtime.h>
#include <math.h>

#define NPTS     4096
#define NB       16
#define NCLOUD   32
#define NBINS    128
#define SORT_TPB 256
#define MAIN_TPB 512
#define BLK_PER_PAIR 8
#define MAIN_GRID (NCLOUD * BLK_PER_PAIR)   // 256

__device__ __align__(16) float g_sx[NCLOUD][NPTS];
__device__ __align__(16) float g_sy[NCLOUD][NPTS];
__device__ __align__(16) float g_sz[NCLOUD][NPTS];
__device__ __align__(16) float g_su[NCLOUD][NPTS];
__device__ int   g_binstart[NCLOUD][NBINS + 1];
__device__ float g_zmin[NCLOUD];
__device__ float g_binw[NCLOUD];
__device__ float g_accum;       // zero at entry/exit of every launch
__device__ unsigned g_count;    // zero at entry/exit of every launch

typedef unsigned long long u64;

static __device__ __forceinline__ u64 bcast2(float v) {
    u64 r;
    asm("mov.b64 %0, {%1, %1};" : "=l"(r) : "f"(v));
    return r;
}
static __device__ __forceinline__ void unpack2(u64 v, float &lo, float &hi) {
    asm("mov.b64 {%0, %1}, %2;" : "=f"(lo), "=f"(hi) : "l"(v));
}
static __device__ __forceinline__ u64 fma2(u64 a, u64 b, u64 c) {
    u64 d;
    asm("fma.rn.f32x2 %0, %1, %2, %3;" : "=l"(d) : "l"(a), "l"(b), "l"(c));
    return d;
}

// ---------------- sort kernel: bucket each cloud by z into NBINS bins -------
__global__ void __launch_bounds__(SORT_TPB) sort_kernel(const float* __restrict__ tpl,
                                                        const float* __restrict__ src) {
    const int c = blockIdx.x;   // 0..15 = template batches, 16..31 = source
    const float* P = (c < NB) ? (tpl + (size_t)c * NPTS * 3)
                              : (src + (size_t)(c - NB) * NPTS * 3);
    __shared__ float rmin[SORT_TPB / 32], rmax[SORT_TPB / 32];
    __shared__ int hist[NBINS];
    __shared__ int scan_a[NBINS], scan_b[NBINS];
    __shared__ int boff[NBINS + 1];
    __shared__ float s_zmin, s_inv;

    const int tid = threadIdx.x;
    float mn = 3.4e38f, mx = -3.4e38f;
    for (int p = tid; p < NPTS; p += SORT_TPB) {
        float z = P[3 * p + 2];
        mn = fminf(mn, z);
        mx = fmaxf(mx, z);
    }
#pragma unroll
    for (int o = 16; o; o >>= 1) {
        mn = fminf(mn, __shfl_xor_sync(0xffffffffu, mn, o));
        mx = fmaxf(mx, __shfl_xor_sync(0xffffffffu, mx, o));
    }
    if ((tid & 31) == 0) { rmin[tid >> 5] = mn; rmax[tid >> 5] = mx; }
    if (tid < NBINS) hist[tid] = 0;
    __syncthreads();
    if (tid == 0) {
        float zmin = rmin[0], zmax = rmax[0];
        for (int w = 1; w < SORT_TPB / 32; w++) {
            zmin = fminf(zmin, rmin[w]);
            zmax = fmaxf(zmax, rmax[w]);
        }
        float binw = fmaxf((zmax - zmin) / NBINS, 1e-30f);
        s_zmin = zmin;
        s_inv = 1.0f / binw;
        g_zmin[c] = zmin;
        g_binw[c] = binw;
    }
    __syncthreads();
    const float zmin = s_zmin, inv = s_inv;

    for (int p = tid; p < NPTS; p += SORT_TPB) {
        float z = P[3 * p + 2];
        int bn = min(max((int)((z - zmin) * inv), 0), NBINS - 1);
        atomicAdd(&hist[bn], 1);
    }
    __syncthreads();

    // parallel inclusive scan (Hillis-Steele) over NBINS
    if (tid < NBINS) scan_a[tid] = hist[tid];
    __syncthreads();
    int* cur = scan_a;
    int* nxt = scan_b;
#pragma unroll
    for (int off = 1; off < NBINS; off <<= 1) {
        if (tid < NBINS)
            nxt[tid] = (tid >= off) ? cur[tid] + cur[tid - off] : cur[tid];
        __syncthreads();
        int* t = cur; cur = nxt; nxt = t;
    }
    if (tid < NBINS) boff[tid] = cur[tid] - hist[tid];   // exclusive
    if (tid == 0) boff[NBINS] = NPTS;
    __syncthreads();
    if (tid < NBINS) hist[tid] = 0;
    __syncthreads();

    for (int p = tid; p < NPTS; p += SORT_TPB) {
        float x = P[3 * p + 0], y = P[3 * p + 1], z = P[3 * p + 2];
        int bn = min(max((int)((z - zmin) * inv), 0), NBINS - 1);
        int idx = boff[bn] + atomicAdd(&hist[bn], 1);
        g_sx[c][idx] = x;
        g_sy[c][idx] = y;
        g_sz[c][idx] = z;
        g_su[c][idx] = x * x + y * y + z * z;
    }
    for (int k = tid; k <= NBINS; k += SORT_TPB) g_binstart[c][k] = boff[k];
}

// ---------- main kernel: smem-staged windowed NN scan, batched expansion ----
__global__ void __launch_bounds__(MAIN_TPB, 2) chamfer_main(float* __restrict__ out) {
    extern __shared__ float sm[];
    float* sx = sm;
    float* sy = sm + NPTS;
    float* sz = sm + 2 * NPTS;
    float* su = sm + 3 * NPTS;
    int* sbin = (int*)(sm + 4 * NPTS);        // NBINS+1 ints
    float* red = (float*)(sbin + NBINS + 1);  // MAIN_TPB/32 floats

    const int tid = threadIdx.x;
    const int b = blockIdx.x;
    const int pair = b >> 3;                  // 0..31
    const int blk  = b & 7;
    const int dir = pair >> 4;
    const int batch = pair & 15;
    const int qcl = (dir == 0) ? batch : NB + batch;
    const int dcl = (dir == 0) ? NB + batch : batch;

    for (int p = tid; p < NPTS; p += MAIN_TPB) {
        sx[p] = g_sx[dcl][p];
        sy[p] = g_sy[dcl][p];
        sz[p] = g_sz[dcl][p];
        su[p] = g_su[dcl][p];
    }
    for (int k = tid; k <= NBINS; k += MAIN_TPB) sbin[k] = g_binstart[dcl][k];
    __syncthreads();

    const float zmin = g_zmin[dcl];
    const float binw = g_binw[dcl];
    const float invw = 1.0f / binw;

    const int warp = tid >> 5, lane = tid & 31;
    const int q = blk * MAIN_TPB + warp * 32 + lane;   // sorted query index

    const float qz = g_sz[qcl][q];
    const float qu = g_su[qcl][q];
    const u64 pqx = bcast2(-2.0f * g_sx[qcl][q]);
    const u64 pqy = bcast2(-2.0f * g_sy[qcl][q]);
    const u64 pqz = bcast2(-2.0f * qz);

    float wlo = qz, whi = qz;
#pragma unroll
    for (int o = 16; o; o >>= 1) {
        wlo = fminf(wlo, __shfl_xor_sync(0xffffffffu, wlo, o));
        whi = fmaxf(whi, __shfl_xor_sync(0xffffffffu, whi, o));
    }
    int lo = min(max((int)((wlo - zmin) * invw), 0), NBINS - 1);
    int hi = min(max((int)((whi - zmin) * invw), 0), NBINS - 1);

    float bA = 3.4e38f, bB = 3.4e38f;
    const ulonglong2* vx = (const ulonglong2*)sx;
    const ulonglong2* vy = (const ulonglong2*)sy;
    const ulonglong2* vz = (const ulonglong2*)sz;
    const ulonglong2* vu = (const ulonglong2*)su;

    auto scan = [&](int a, int e) {
        int j1 = (e + 3) >> 2;
#pragma unroll 2
        for (int j = a >> 2; j < j1; j++) {
            ulonglong2 bx = vx[j], by = vy[j], bz = vz[j], bu = vu[j];
            u64 a01 = fma2(pqz, bz.x, bu.x);
            a01 = fma2(pqy, by.x, a01);
            a01 = fma2(pqx, bx.x, a01);
            u64 a23 = fma2(pqz, bz.y, bu.y);
            a23 = fma2(pqy, by.y, a23);
            a23 = fma2(pqx, bx.y, a23);
            float l0, h0, l1, h1;
            unpack2(a01, l0, h0);
            unpack2(a23, l1, h1);
            bA = fminf(bA, fminf(l0, l1));
            bB = fminf(bB, fminf(h0, h1));
        }
    };

    // initial window: bins spanned by the warp's queries
    scan(sbin[lo], sbin[hi + 1]);

    // batched expansion: admit ALL bins within radius r = sqrt(warp_max(dist2))
    // per round; the radius only shrinks, so a stable window is final.
    while (true) {
        float m = qu + fminf(bA, bB);
#pragma unroll
        for (int o = 16; o; o >>= 1) m = fmaxf(m, __shfl_xor_sync(0xffffffffu, m, o));
        m = fmaxf(m, 0.0f);
        float r = sqrtf(m) * 1.0001f + 1e-12f;
        int nlo = max(min((int)((wlo - r - zmin) * invw), NBINS - 1), 0);
        int nhi = min(max((int)((whi + r - zmin) * invw), 0), NBINS - 1);
        bool grewL = nlo < lo, grewR = nhi > hi;
        if (!grewL && !grewR) break;
        if (grewL) {
            scan(sbin[nlo], sbin[lo]);
            lo = nlo;
        }
        if (grewR) {
            scan(sbin[hi + 1], sbin[nhi + 1]);
            hi = nhi;
        }
    }

    float s = sqrtf(fmaxf(qu + fminf(bA, bB), 0.0f));

    // block reduction
#pragma unroll
    for (int o = 16; o; o >>= 1) s += __shfl_xor_sync(0xffffffffu, s, o);
    if (lane == 0) red[warp] = s;
    __syncthreads();
    if (tid == 0) {
        float t = 0.0f;
#pragma unroll
        for (int w = 0; w < MAIN_TPB / 32; w++) t += red[w];
        atomicAdd(&g_accum, t);
        __threadfence();
        unsigned old = atomicAdd(&g_count, 1u);
        if (old == MAIN_GRID - 1) {
            __threadfence();
            float total = atomicAdd(&g_accum, 0.0f);
            out[0] = total * (1.0f / 131072.0f);   // / (2*16*4096)
            g_accum = 0.0f;
            __threadfence();
            atomicExch(&g_count, 0u);
        }
    }
}

extern "C" void kernel_launch(void* const* d_in, const int* in_sizes, int n_in,
                              void* d_out, int out_size) {
    const float* tpl = (const float*)d_in[0];
    const float* src = (const float*)d_in[1];
    (void)in_sizes; (void)n_in; (void)out_size;

    const int smem = 4 * NPTS * (int)sizeof(float)
                   + (NBINS + 1) * (int)sizeof(int)
                   + (MAIN_TPB / 32) * (int)sizeof(float);
    cudaFuncSetAttribute(chamfer_main, cudaFuncAttributeMaxDynamicSharedMemorySize, smem);

    sort_kernel<<<NCLOUD, SORT_TPB>>>(tpl, src);
    chamfer_main<<<MAIN_GRID, MAIN_TPB, smem>>>((float*)d_out);
}

// round 10
// speedup vs baseline: 2.1640x; 1.2123x over previous
#include <cuda_runtime.h>
#include <math.h>

#define NPTS     4096
#define NB       16
#define NCLOUD   32
#define NBINS    128
#define SORT_TPB 256
#define MAIN_TPB 256
#define BLK_PER_PAIR 8
#define MAIN_GRID (NCLOUD * BLK_PER_PAIR)   // 256 blocks, 8 warps each
// warp handles 64 consecutive sorted queries (2 per lane); 64 chunks per pair.

__device__ __align__(16) float g_sx[NCLOUD][NPTS];
__device__ __align__(16) float g_sy[NCLOUD][NPTS];
__device__ __align__(16) float g_sz[NCLOUD][NPTS];
__device__ __align__(16) float g_su[NCLOUD][NPTS];
__device__ int   g_binstart[NCLOUD][NBINS + 1];
__device__ float g_zmin[NCLOUD];
__device__ float g_binw[NCLOUD];
__device__ float g_accum;       // zero at entry/exit of every launch
__device__ unsigned g_count;    // zero at entry/exit of every launch

typedef unsigned long long u64;

static __device__ __forceinline__ u64 bcast2(float v) {
    u64 r;
    asm("mov.b64 %0, {%1, %1};" : "=l"(r) : "f"(v));
    return r;
}
static __device__ __forceinline__ void unpack2(u64 v, float &lo, float &hi) {
    asm("mov.b64 {%0, %1}, %2;" : "=f"(lo), "=f"(hi) : "l"(v));
}
static __device__ __forceinline__ u64 fma2(u64 a, u64 b, u64 c) {
    u64 d;
    asm("fma.rn.f32x2 %0, %1, %2, %3;" : "=l"(d) : "l"(a), "l"(b), "l"(c));
    return d;
}

// ---------------- sort kernel: bucket each cloud by z into NBINS bins -------
__global__ void __launch_bounds__(SORT_TPB) sort_kernel(const float* __restrict__ tpl,
                                                        const float* __restrict__ src) {
    const int c = blockIdx.x;
    const float* P = (c < NB) ? (tpl + (size_t)c * NPTS * 3)
                              : (src + (size_t)(c - NB) * NPTS * 3);
    __shared__ float rmin[SORT_TPB / 32], rmax[SORT_TPB / 32];
    __shared__ int hist[NBINS];
    __shared__ int scan_a[NBINS], scan_b[NBINS];
    __shared__ int boff[NBINS + 1];
    __shared__ float s_zmin, s_inv;

    const int tid = threadIdx.x;
    float mn = 3.4e38f, mx = -3.4e38f;
    for (int p = tid; p < NPTS; p += SORT_TPB) {
        float z = P[3 * p + 2];
        mn = fminf(mn, z);
        mx = fmaxf(mx, z);
    }
#pragma unroll
    for (int o = 16; o; o >>= 1) {
        mn = fminf(mn, __shfl_xor_sync(0xffffffffu, mn, o));
        mx = fmaxf(mx, __shfl_xor_sync(0xffffffffu, mx, o));
    }
    if ((tid & 31) == 0) { rmin[tid >> 5] = mn; rmax[tid >> 5] = mx; }
    if (tid < NBINS) hist[tid] = 0;
    __syncthreads();
    if (tid == 0) {
        float zmin = rmin[0], zmax = rmax[0];
        for (int w = 1; w < SORT_TPB / 32; w++) {
            zmin = fminf(zmin, rmin[w]);
            zmax = fmaxf(zmax, rmax[w]);
        }
        float binw = fmaxf((zmax - zmin) / NBINS, 1e-30f);
        s_zmin = zmin;
        s_inv = 1.0f / binw;
        g_zmin[c] = zmin;
        g_binw[c] = binw;
    }
    __syncthreads();
    const float zmin = s_zmin, inv = s_inv;

    for (int p = tid; p < NPTS; p += SORT_TPB) {
        float z = P[3 * p + 2];
        int bn = min(max((int)((z - zmin) * inv), 0), NBINS - 1);
        atomicAdd(&hist[bn], 1);
    }
    __syncthreads();

    if (tid < NBINS) scan_a[tid] = hist[tid];
    __syncthreads();
    int* cur = scan_a;
    int* nxt = scan_b;
#pragma unroll
    for (int off = 1; off < NBINS; off <<= 1) {
        if (tid < NBINS)
            nxt[tid] = (tid >= off) ? cur[tid] + cur[tid - off] : cur[tid];
        __syncthreads();
        int* t = cur; cur = nxt; nxt = t;
    }
    if (tid < NBINS) boff[tid] = cur[tid] - hist[tid];
    if (tid == 0) boff[NBINS] = NPTS;
    __syncthreads();
    if (tid < NBINS) hist[tid] = 0;
    __syncthreads();

    for (int p = tid; p < NPTS; p += SORT_TPB) {
        float x = P[3 * p + 0], y = P[3 * p + 1], z = P[3 * p + 2];
        int bn = min(max((int)((z - zmin) * inv), 0), NBINS - 1);
        int idx = boff[bn] + atomicAdd(&hist[bn], 1);
        g_sx[c][idx] = x;
        g_sy[c][idx] = y;
        g_sz[c][idx] = z;
        g_su[c][idx] = x * x + y * y + z * z;
    }
    for (int k = tid; k <= NBINS; k += SORT_TPB) g_binstart[c][k] = boff[k];
}

// ---------- main: smem scan, batched expansion, striped chunk->block map ----
__global__ void __launch_bounds__(MAIN_TPB, 3) chamfer_main(float* __restrict__ out) {
    extern __shared__ float sm[];
    float* sx = sm;
    float* sy = sm + NPTS;
    float* sz = sm + 2 * NPTS;
    float* su = sm + 3 * NPTS;
    int* sbin = (int*)(sm + 4 * NPTS);
    float* red = (float*)(sbin + NBINS + 1);

    const int tid = threadIdx.x;
    const int b = blockIdx.x;
    const int pair = b >> 3;                  // 0..31
    const int blk  = b & 7;
    const int dir = pair >> 4;
    const int batch = pair & 15;
    const int qcl = (dir == 0) ? batch : NB + batch;
    const int dcl = (dir == 0) ? NB + batch : batch;

    for (int p = tid; p < NPTS; p += MAIN_TPB) {
        sx[p] = g_sx[dcl][p];
        sy[p] = g_sy[dcl][p];
        sz[p] = g_sz[dcl][p];
        su[p] = g_su[dcl][p];
    }
    for (int k = tid; k <= NBINS; k += MAIN_TPB) sbin[k] = g_binstart[dcl][k];
    __syncthreads();

    const float zmin = g_zmin[dcl];
    const float binw = g_binw[dcl];
    const float invw = 1.0f / binw;

    const int warp = tid >> 5, lane = tid & 31;
    // striped mapping: block gets chunks {blk, blk+8, ..., blk+56} of its pair
    // -> every block samples the full z-range uniformly (easy+hard mix).
    const int chunk = warp * BLK_PER_PAIR + blk;    // 0..63
    const int q0 = chunk * 64 + lane;
    const int q1 = q0 + 32;

    const float qz0 = g_sz[qcl][q0], qu0 = g_su[qcl][q0];
    const float qz1 = g_sz[qcl][q1], qu1 = g_su[qcl][q1];
    const u64 pqx0 = bcast2(-2.0f * g_sx[qcl][q0]);
    const u64 pqy0 = bcast2(-2.0f * g_sy[qcl][q0]);
    const u64 pqz0 = bcast2(-2.0f * qz0);
    const u64 pqx1 = bcast2(-2.0f * g_sx[qcl][q1]);
    const u64 pqy1 = bcast2(-2.0f * g_sy[qcl][q1]);
    const u64 pqz1 = bcast2(-2.0f * qz1);

    float wlo = fminf(qz0, qz1), whi = fmaxf(qz0, qz1);
#pragma unroll
    for (int o = 16; o; o >>= 1) {
        wlo = fminf(wlo, __shfl_xor_sync(0xffffffffu, wlo, o));
        whi = fmaxf(whi, __shfl_xor_sync(0xffffffffu, whi, o));
    }
    int lo = min(max((int)((wlo - zmin) * invw), 0), NBINS - 1);
    int hi = min(max((int)((whi - zmin) * invw), 0), NBINS - 1);

    float b0A = 3.4e38f, b0B = 3.4e38f, b1A = 3.4e38f, b1B = 3.4e38f;
    const ulonglong2* vx = (const ulonglong2*)sx;
    const ulonglong2* vy = (const ulonglong2*)sy;
    const ulonglong2* vz = (const ulonglong2*)sz;
    const ulonglong2* vu = (const ulonglong2*)su;

    auto scan = [&](int a, int e) {
        int j1 = (e + 3) >> 2;
#pragma unroll 2
        for (int j = a >> 2; j < j1; j++) {
            ulonglong2 bx = vx[j], by = vy[j], bz = vz[j], bu = vu[j];
            u64 a01 = fma2(pqz0, bz.x, bu.x);
            a01 = fma2(pqy0, by.x, a01);
            a01 = fma2(pqx0, bx.x, a01);
            u64 a23 = fma2(pqz0, bz.y, bu.y);
            a23 = fma2(pqy0, by.y, a23);
            a23 = fma2(pqx0, bx.y, a23);
            u64 c01 = fma2(pqz1, bz.x, bu.x);
            c01 = fma2(pqy1, by.x, c01);
            c01 = fma2(pqx1, bx.x, c01);
            u64 c23 = fma2(pqz1, bz.y, bu.y);
            c23 = fma2(pqy1, by.y, c23);
            c23 = fma2(pqx1, bx.y, c23);
            float l0, h0, l1, h1;
            unpack2(a01, l0, h0);
            unpack2(a23, l1, h1);
            b0A = fminf(b0A, fminf(l0, l1));
            b0B = fminf(b0B, fminf(h0, h1));
            unpack2(c01, l0, h0);
            unpack2(c23, l1, h1);
            b1A = fminf(b1A, fminf(l0, l1));
            b1B = fminf(b1B, fminf(h0, h1));
        }
    };

    // initial window: bins spanned by the warp's 64 queries
    scan(sbin[lo], sbin[hi + 1]);

    // batched expansion to radius r = sqrt(warp_max(best dist^2))
    while (true) {
        float m = fmaxf(qu0 + fminf(b0A, b0B), qu1 + fminf(b1A, b1B));
#pragma unroll
        for (int o = 16; o; o >>= 1) m = fmaxf(m, __shfl_xor_sync(0xffffffffu, m, o));
        m = fmaxf(m, 0.0f);
        float r = sqrtf(m) * 1.0001f + 1e-12f;
        int nlo = max(min((int)((wlo - r - zmin) * invw), NBINS - 1), 0);
        int nhi = min(max((int)((whi + r - zmin) * invw), 0), NBINS - 1);
        bool grewL = nlo < lo, grewR = nhi > hi;
        if (!grewL && !grewR) break;
        if (grewL) { scan(sbin[nlo], sbin[lo]); lo = nlo; }
        if (grewR) { scan(sbin[hi + 1], sbin[nhi + 1]); hi = nhi; }
    }

    float s = sqrtf(fmaxf(qu0 + fminf(b0A, b0B), 0.0f))
            + sqrtf(fmaxf(qu1 + fminf(b1A, b1B), 0.0f));

    // block reduction (8 warps)
#pragma unroll
    for (int o = 16; o; o >>= 1) s += __shfl_xor_sync(0xffffffffu, s, o);
    if (lane == 0) red[warp] = s;
    __syncthreads();
    if (tid == 0) {
        float t = 0.0f;
#pragma unroll
        for (int w = 0; w < MAIN_TPB / 32; w++) t += red[w];
        atomicAdd(&g_accum, t);
        __threadfence();
        unsigned old = atomicAdd(&g_count, 1u);
        if (old == MAIN_GRID - 1) {
            __threadfence();
            float total = atomicAdd(&g_accum, 0.0f);
            out[0] = total * (1.0f / 131072.0f);   // / (2*16*4096)
            g_accum = 0.0f;
            __threadfence();
            atomicExch(&g_count, 0u);
        }
    }
}

extern "C" void kernel_launch(void* const* d_in, const int* in_sizes, int n_in,
                              void* d_out, int out_size) {
    const float* tpl = (const float*)d_in[0];
    const float* src = (const float*)d_in[1];
    (void)in_sizes; (void)n_in; (void)out_size;

    const int smem = 4 * NPTS * (int)sizeof(float)
                   + (NBINS + 1) * (int)sizeof(int)
                   + (MAIN_TPB / 32) * (int)sizeof(float);
    cudaFuncSetAttribute(chamfer_main, cudaFuncAttributeMaxDynamicSharedMemorySize, smem);

    sort_kernel<<<NCLOUD, SORT_TPB>>>(tpl, src);
    chamfer_main<<<MAIN_GRID, MAIN_TPB, smem>>>((float*)d_out);
}